// round 15
// baseline (speedup 1.0000x reference)
#include <cuda_runtime.h>
#include <cuda.h>
#include <cuda_bf16.h>
#include <cuda_fp8.h>
#include <cstdint>

// Problem shape: x[4,2048,4096] -> M=8192, W[4096,4096], b[4096]
#define MROWS 8192
#define DIN   4096
#define DOUT  4096

// GEMM tiling: CTA 128x128, 8 warps (4 M x 2 N), warp tile 32x64, 2 CTAs/SM
static constexpr int BM = 128;
static constexpr int BN = 128;
static constexpr int BKB = 128;              // K bytes per stage (one SW128 row)
static constexpr int KITERS = DIN / BKB;     // 32
static constexpr int STAGES = 3;
static constexpr int A_BYTES = BM * BKB;     // 16384
static constexpr int B_BYTES = BN * BKB;     // 16384
static constexpr int TX_BYTES = A_BYTES + B_BYTES;

// SMEM layout
static constexpr int SM_FULL  = 0;
static constexpr int SM_EMPTY = SM_FULL + 8 * STAGES;
static constexpr int SM_A     = 1024;
static constexpr int SM_B     = SM_A + STAGES * A_BYTES;        // 50176
static constexpr int SMEM_TOTAL = SM_B + STAGES * B_BYTES;      // 99328 -> 2 CTAs/SM

// Single-wave persistent grids: 148 SMs x 8 CTAs (256thr/32reg) = 1184 concurrent.
// Split 2:1 to match the x:W data ratio.
static constexpr int AX_BLOCKS = 790;
static constexpr int AW_BLOCKS = 394;
static constexpr int QX_BLOCKS = 790;
static constexpr int QW_BLOCKS = 394;
static constexpr int PART_MAX  = 1024;   // >= max(AX_BLOCKS, AW_BLOCKS)

// ---------------- scratch ----------------
__device__ uint8_t g_xq[(size_t)MROWS * DIN];
__device__ uint8_t g_wq[(size_t)DOUT * DIN];
__device__ float g_part_x[PART_MAX];
__device__ float g_part_w[PART_MAX];
__device__ float g_scale;   // sx*sw

// ---------------- PTX helpers ----------------
__device__ __forceinline__ uint32_t smem_u32(const void* p) {
    return (uint32_t)__cvta_generic_to_shared(p);
}

#define MBAR_INIT(addr, cnt) \
    asm volatile("mbarrier.init.shared.b64 [%0], %1;" :: "r"(addr), "r"((uint32_t)(cnt)) : "memory")

#define MBAR_EXPECT_TX(addr, bytes) \
    asm volatile("mbarrier.arrive.expect_tx.shared.b64 _, [%0], %1;" \
                 :: "r"(addr), "r"((uint32_t)(bytes)) : "memory")

#define MBAR_ARRIVE(addr) \
    asm volatile("mbarrier.arrive.shared.b64 _, [%0];" :: "r"(addr) : "memory")

#define MBAR_WAIT(addr, parity) do {                                            \
    asm volatile("{\n\t.reg .pred P1;\n\t"                                      \
        "WAIT_LOOP_%=:\n\t"                                                     \
        "mbarrier.try_wait.parity.acquire.cta.shared::cta.b64 P1, [%0], %1, 0x989680;\n\t" \
        "@P1 bra.uni WAIT_DONE_%=;\n\t"                                         \
        "bra.uni WAIT_LOOP_%=;\n\t"                                             \
        "WAIT_DONE_%=:\n\t}"                                                    \
        :: "r"(addr), "r"((uint32_t)(parity)) : "memory");                      \
} while (0)

#define MBAR_WAIT_RELAXED(addr, parity) do {                                    \
    asm volatile("{\n\t.reg .pred P1;\n\t"                                      \
        "WAIT_LOOP_%=:\n\t"                                                     \
        "mbarrier.try_wait.parity.relaxed.cta.shared::cta.b64 P1, [%0], %1, 0x989680;\n\t" \
        "@P1 bra.uni WAIT_DONE_%=;\n\t"                                         \
        "bra.uni WAIT_LOOP_%=;\n\t"                                             \
        "WAIT_DONE_%=:\n\t}"                                                    \
        :: "r"(addr), "r"((uint32_t)(parity)) : "memory");                      \
} while (0)

__device__ __forceinline__ void tma_load_2d(uint32_t dst_smem, const CUtensorMap* map,
                                            int cx, int cy, uint32_t mbar) {
    asm volatile(
        "cp.async.bulk.tensor.2d.shared::cta.global.tile.mbarrier::complete_tx::bytes "
        "[%0], [%1, {%2, %3}], [%4];"
        :: "r"(dst_smem), "l"(map), "r"(cx), "r"(cy), "r"(mbar) : "memory");
}

// LDSM: volatile (must stay ordered after the mbarrier acquire wait)
#define LDSM_X4(r0, r1, r2, r3, addr) \
    asm volatile("ldmatrix.sync.aligned.m8n8.x4.shared.b16 {%0,%1,%2,%3}, [%4];" \
                 : "=r"(r0), "=r"(r1), "=r"(r2), "=r"(r3) : "r"(addr))

// MMA: non-volatile — data deps fully constrain it
#define MMA_E4M3(d, a0, a1, a2, a3, b0, b1) \
    asm("mma.sync.aligned.m16n8k32.row.col.f32.e4m3.e4m3.f32 " \
        "{%0,%1,%2,%3}, {%4,%5,%6,%7}, {%8,%9}, {%0,%1,%2,%3};" \
        : "+f"((d)[0]), "+f"((d)[1]), "+f"((d)[2]), "+f"((d)[3]) \
        : "r"(a0), "r"(a1), "r"(a2), "r"(a3), "r"(b0), "r"(b1))

// packed e4m3x2 convert: first operand -> high byte, second -> low byte
#define CVT_E4M3X2(dst16, hi, lo) \
    asm("cvt.rn.satfinite.e4m3x2.f32 %0, %1, %2;" : "=h"(dst16) : "f"(hi), "f"(lo))

// ---------------- block reduce max (256 threads) ----------------
__device__ __forceinline__ float block_max_256(float m, float* sred) {
    #pragma unroll
    for (int o = 16; o > 0; o >>= 1)
        m = fmaxf(m, __shfl_xor_sync(0xFFFFFFFFu, m, o));
    if ((threadIdx.x & 31) == 0) sred[threadIdx.x >> 5] = m;
    __syncthreads();
    if (threadIdx.x < 8) {
        float v = sred[threadIdx.x];
        #pragma unroll
        for (int o = 4; o > 0; o >>= 1)
            v = fmaxf(v, __shfl_xor_sync(0xFFu, v, o));
        if (threadIdx.x == 0) sred[0] = v;
    }
    __syncthreads();
    return sred[0];
}

__device__ __forceinline__ float max4(float4 v) {
    return fmaxf(fmaxf(fabsf(v.x), fabsf(v.y)), fmaxf(fabsf(v.z), fabsf(v.w)));
}

// ---------------- prep kernels ----------------
// Fused amax, single-wave persistent grid. Blocks [0, AX_BLOCKS) -> x, rest -> W.
// x2 unrolled (MLP sweet spot from R13/R14 calibration) with tail guard.
__global__ void amax_kernel(const float* __restrict__ x, const float* __restrict__ W) {
    __shared__ float sred[8];
    const bool isW = blockIdx.x >= AX_BLOCKS;
    const float4* s4 = isW ? (const float4*)W : (const float4*)x;
    const long long n4 = isW ? (long long)DOUT * DIN / 4 : (long long)MROWS * DIN / 4;
    const int nb = isW ? AW_BLOCKS : AX_BLOCKS;
    const int bid = isW ? (int)blockIdx.x - AX_BLOCKS : (int)blockIdx.x;

    float m0 = 0.0f, m1 = 0.0f;
    const long long step = (long long)nb * blockDim.x;
    long long i = (long long)bid * blockDim.x + threadIdx.x;
    for (; i + step < n4; i += 2 * step) {
        float4 a = s4[i];
        float4 b = s4[i + step];
        m0 = fmaxf(m0, max4(a));
        m1 = fmaxf(m1, max4(b));
    }
    if (i < n4) m0 = fmaxf(m0, max4(s4[i]));   // tail (max is order-free)
    float m = block_max_256(fmaxf(m0, m1), sred);
    if (threadIdx.x == 0) (isW ? g_part_w : g_part_x)[bid] = m;
}

// Fused quant, single-wave persistent grid. Blocks [0,QX_BLOCKS) -> x, rest -> W.
// ALU-lean (reciprocal-mul + packed e4m3x2 CVT), x2 unrolled, tail guard.
__global__ void quant_kernel(const float* __restrict__ x, const float* __restrict__ W) {
    __shared__ float sred[8];
    const bool isW = blockIdx.x >= QX_BLOCKS;

    float m = 0.0f;
    if (isW) {
        for (int i = threadIdx.x; i < AW_BLOCKS; i += 256) m = fmaxf(m, g_part_w[i]);
    } else {
        for (int i = threadIdx.x; i < AX_BLOCKS; i += 256) m = fmaxf(m, g_part_x[i]);
    }
    m = block_max_256(m, sred);
    const float r = 448.0f / fmaxf(m, 1e-12f);   // exact once; per-element mul below

    if (blockIdx.x == 0) {
        __syncthreads();
        float mw = 0.0f;
        for (int i = threadIdx.x; i < AW_BLOCKS; i += 256) mw = fmaxf(mw, g_part_w[i]);
        mw = block_max_256(mw, sred);
        if (threadIdx.x == 0)
            g_scale = (fmaxf(m, 1e-12f) / 448.0f) * (fmaxf(mw, 1e-12f) / 448.0f);
    }

    const float4* s4 = isW ? (const float4*)W : (const float4*)x;
    uint8_t* dst = isW ? g_wq : g_xq;
    const long long n4 = isW ? (long long)DOUT * DIN / 4 : (long long)MROWS * DIN / 4;
    const int nb = isW ? QW_BLOCKS : QX_BLOCKS;
    const int bid = isW ? (int)blockIdx.x - QX_BLOCKS : (int)blockIdx.x;

    const long long step = (long long)nb * blockDim.x;
    long long i = (long long)bid * blockDim.x + threadIdx.x;
    for (; i + step < n4; i += 2 * step) {
        float4 a = s4[i];
        float4 b = s4[i + step];
        unsigned short lo0, hi0, lo1, hi1;
        CVT_E4M3X2(lo0, a.y * r, a.x * r);
        CVT_E4M3X2(hi0, a.w * r, a.z * r);
        CVT_E4M3X2(lo1, b.y * r, b.x * r);
        CVT_E4M3X2(hi1, b.w * r, b.z * r);
        *reinterpret_cast<uint32_t*>(dst + i * 4)          = (uint32_t)lo0 | ((uint32_t)hi0 << 16);
        *reinterpret_cast<uint32_t*>(dst + (i + step) * 4) = (uint32_t)lo1 | ((uint32_t)hi1 << 16);
    }
    if (i < n4) {   // tail: exactly-once write
        float4 a = s4[i];
        unsigned short lo0, hi0;
        CVT_E4M3X2(lo0, a.y * r, a.x * r);
        CVT_E4M3X2(hi0, a.w * r, a.z * r);
        *reinterpret_cast<uint32_t*>(dst + i * 4) = (uint32_t)lo0 | ((uint32_t)hi0 << 16);
    }
}

// ---------------- GEMM: TMA pipeline + fp8 mma.sync (frozen round-9/11 winner) ----------------
#define LOAD_FRAGS(ks, A, B) do {                                               \
    _Pragma("unroll")                                                           \
    for (int mt = 0; mt < 2; ++mt)                                              \
        LDSM_X4((A)[mt][0], (A)[mt][1], (A)[mt][2], (A)[mt][3],                 \
                aBase + mt * (16 * BKB) + cAo[ks]);                             \
    _Pragma("unroll")                                                           \
    for (int g = 0; g < 4; ++g)                                                 \
        LDSM_X4((B)[2*g][0], (B)[2*g][1], (B)[2*g+1][0], (B)[2*g+1][1],         \
                bBase + g * (16 * BKB) + cBo[ks]);                              \
} while (0)

#define MMA_BURST(A, B) do {                                                    \
    _Pragma("unroll")                                                           \
    for (int mt = 0; mt < 2; ++mt)                                              \
        _Pragma("unroll")                                                       \
        for (int nt = 0; nt < 8; ++nt)                                          \
            MMA_E4M3(acc[mt][nt],                                               \
                     (A)[mt][0], (A)[mt][1], (A)[mt][2], (A)[mt][3],            \
                     (B)[nt][0], (B)[nt][1]);                                   \
} while (0)

__global__ void __launch_bounds__(256, 2) gemm_kernel(
    const __grid_constant__ CUtensorMap tma_a,
    const __grid_constant__ CUtensorMap tma_b,
    const float* __restrict__ bias,
    float* __restrict__ out)
{
    extern __shared__ __align__(1024) char smem[];
    const uint32_t sbase = smem_u32(smem);
    const int tid  = threadIdx.x;
    const int wid  = tid >> 5;
    const int lane = tid & 31;
    const int warpM = wid & 3;    // 0..3 (32 rows each)
    const int warpN = wid >> 2;   // 0..1 (64 cols each)

    if (tid == 0) {
        #pragma unroll
        for (int s = 0; s < STAGES; s++) {
            MBAR_INIT(sbase + SM_FULL + 8 * s, 1);
            MBAR_INIT(sbase + SM_EMPTY + 8 * s, 8);
        }
        asm volatile("fence.proxy.async.shared::cta;" ::: "memory");
    }
    __syncthreads();

    const int mbase = (int)blockIdx.y * BM;
    const int nbase = (int)blockIdx.x * BN;

    // prologue: fill STAGES-1 stages
    if (tid == 0) {
        #pragma unroll
        for (int f = 0; f < STAGES - 1; ++f) {
            MBAR_EXPECT_TX(sbase + SM_FULL + 8 * f, TX_BYTES);
            tma_load_2d(sbase + SM_A + f * A_BYTES, &tma_a, f * BKB, mbase, sbase + SM_FULL + 8 * f);
            tma_load_2d(sbase + SM_B + f * B_BYTES, &tma_b, f * BKB, nbase, sbase + SM_FULL + 8 * f);
        }
    }

    // per-lane ldmatrix address precompute (SW128 swizzle: 16B-chunk ^ (row & 7))
    const int l8 = lane & 7;
    const int rowA  = warpM * 32 + l8 + 8 * ((lane >> 3) & 1);
    const int halfA = lane >> 4;
    const int swzA  = rowA & 7;
    const uint32_t aRowOff = (uint32_t)rowA * BKB;
    const int rowB  = warpN * 64 + l8 + 8 * (lane >> 4);
    const int halfB = (lane >> 3) & 1;
    const int swzB  = rowB & 7;
    const uint32_t bRowOff = (uint32_t)rowB * BKB;

    // precomputed swizzled chunk offsets for the 4 k32 slices (loop-invariant)
    uint32_t cAo[4], cBo[4];
    #pragma unroll
    for (int ks = 0; ks < 4; ++ks) {
        cAo[ks] = (uint32_t)((((ks << 1) | halfA) ^ swzA) << 4);
        cBo[ks] = (uint32_t)((((ks << 1) | halfB) ^ swzB) << 4);
    }

    float acc[2][8][4];
    #pragma unroll
    for (int mt = 0; mt < 2; ++mt)
        #pragma unroll
        for (int nt = 0; nt < 8; ++nt)
            #pragma unroll
            for (int r = 0; r < 4; ++r) acc[mt][nt][r] = 0.0f;

    uint32_t afr[2][2][4];
    uint32_t bfr[2][8][2];

    // unroll by STAGES so stage indices fold to immediates without a 50KB body
    #pragma unroll 3
    for (int i = 0; i < KITERS; ++i) {
        const int s = i % STAGES;
        const uint32_t ph = (uint32_t)((i / STAGES) & 1);

        // rotate TMA producer duty across warps: iteration f's producer is warp (f & 7)
        {
            const int f = i + STAGES - 1;
            if (f < KITERS && wid == (f & 7) && lane == 0) {
                const int fs = f % STAGES;
                if (f >= STAGES) {
                    MBAR_WAIT_RELAXED(sbase + SM_EMPTY + 8 * fs,
                                      (uint32_t)(((f - STAGES) / STAGES) & 1));
                }
                MBAR_EXPECT_TX(sbase + SM_FULL + 8 * fs, TX_BYTES);
                tma_load_2d(sbase + SM_A + fs * A_BYTES, &tma_a, f * BKB, mbase, sbase + SM_FULL + 8 * fs);
                tma_load_2d(sbase + SM_B + fs * B_BYTES, &tma_b, f * BKB, nbase, sbase + SM_FULL + 8 * fs);
            }
        }

        MBAR_WAIT(sbase + SM_FULL + 8 * s, ph);

        const uint32_t aBase = sbase + SM_A + s * A_BYTES + aRowOff;
        const uint32_t bBase = sbase + SM_B + s * B_BYTES + bRowOff;

        // round-7 slice schedule: empty-arrive fires after the LAST LDSM
        LOAD_FRAGS(0, afr[0], bfr[0]);
        LOAD_FRAGS(1, afr[1], bfr[1]);
        MMA_BURST(afr[0], bfr[0]);
        LOAD_FRAGS(2, afr[0], bfr[0]);
        MMA_BURST(afr[1], bfr[1]);
        LOAD_FRAGS(3, afr[1], bfr[1]);
        if (lane == 0) MBAR_ARRIVE(sbase + SM_EMPTY + 8 * s);   // early release
        MMA_BURST(afr[0], bfr[0]);
        MMA_BURST(afr[1], bfr[1]);
    }

    // ---- epilogue ----
    const float sc = g_scale;
    const int orow0 = mbase + warpM * 32 + (lane >> 2);
    const int ocol0 = nbase + warpN * 64 + (lane & 3) * 2;

    #pragma unroll
    for (int mt = 0; mt < 2; ++mt) {
        #pragma unroll
        for (int nt = 0; nt < 8; ++nt) {
            const int col = ocol0 + nt * 8;
            const float2 bb = *reinterpret_cast<const float2*>(bias + col);
            const int r0 = orow0 + mt * 16;
            float2 v0, v1;
            v0.x = acc[mt][nt][0] * sc + bb.x;
            v0.y = acc[mt][nt][1] * sc + bb.y;
            v1.x = acc[mt][nt][2] * sc + bb.x;
            v1.y = acc[mt][nt][3] * sc + bb.y;
            *reinterpret_cast<float2*>(out + (size_t)r0 * DOUT + col) = v0;
            *reinterpret_cast<float2*>(out + (size_t)(r0 + 8) * DOUT + col) = v1;
        }
    }
}

// ---------------- host launch ----------------
typedef CUresult (*EncodeFn)(CUtensorMap*, CUtensorMapDataType, cuuint32_t, void*,
                             const cuuint64_t*, const cuuint64_t*, const cuuint32_t*,
                             const cuuint32_t*, CUtensorMapInterleave, CUtensorMapSwizzle,
                             CUtensorMapL2promotion, CUtensorMapFloatOOBfill);

static void make_map(EncodeFn enc, CUtensorMap* map, void* base,
                     uint64_t dim0, uint64_t dim1, uint32_t box0, uint32_t box1) {
    cuuint64_t dims[2]    = {dim0, dim1};
    cuuint64_t strides[1] = {dim0};   // 1 byte per element
    cuuint32_t box[2]     = {box0, box1};
    cuuint32_t estr[2]    = {1, 1};
    enc(map, CU_TENSOR_MAP_DATA_TYPE_UINT8, 2, base, dims, strides, box, estr,
        CU_TENSOR_MAP_INTERLEAVE_NONE, CU_TENSOR_MAP_SWIZZLE_128B,
        CU_TENSOR_MAP_L2_PROMOTION_L2_128B, CU_TENSOR_MAP_FLOAT_OOB_FILL_NONE);
}

extern "C" void kernel_launch(void* const* d_in, const int* in_sizes, int n_in,
                              void* d_out, int out_size) {
    const float* x    = (const float*)d_in[0];
    const float* W    = (const float*)d_in[1];
    const float* bias = (const float*)d_in[2];
    float* out        = (float*)d_out;

    void *xq_ptr = nullptr, *wq_ptr = nullptr;
    cudaGetSymbolAddress(&xq_ptr, g_xq);
    cudaGetSymbolAddress(&wq_ptr, g_wq);

    EncodeFn enc = nullptr;
    cudaDriverEntryPointQueryResult qres;
    cudaGetDriverEntryPointByVersion("cuTensorMapEncodeTiled", (void**)&enc, 12000,
                                     cudaEnableDefault, &qres);

    CUtensorMap tma_a, tma_b;
    make_map(enc, &tma_a, xq_ptr, DIN, MROWS, BKB, BM);
    make_map(enc, &tma_b, wq_ptr, DIN, DOUT, BKB, BN);

    cudaFuncSetAttribute(gemm_kernel, cudaFuncAttributeMaxDynamicSharedMemorySize, SMEM_TOTAL);

    // 3 launches: fused amax (single wave), fused quant (single wave), gemm.
    amax_kernel<<<AX_BLOCKS + AW_BLOCKS, 256>>>(x, W);
    quant_kernel<<<QX_BLOCKS + QW_BLOCKS, 256>>>(x, W);

    dim3 grid(DOUT / BN, MROWS / BM);   // (32, 64)
    gemm_kernel<<<grid, 256, SMEM_TOTAL>>>(tma_a, tma_b, bias, out);
}

// round 16
// speedup vs baseline: 1.0021x; 1.0021x over previous
#include <cuda_runtime.h>
#include <cuda.h>
#include <cuda_bf16.h>
#include <cuda_fp8.h>
#include <cstdint>

// Problem shape: x[4,2048,4096] -> M=8192, W[4096,4096], b[4096]
#define MROWS 8192
#define DIN   4096
#define DOUT  4096

// GEMM tiling: CTA 128x128, 8 warps (4 M x 2 N), warp tile 32x64, 2 CTAs/SM
static constexpr int BM = 128;
static constexpr int BN = 128;
static constexpr int BKB = 128;              // K bytes per stage (one SW128 row)
static constexpr int KITERS = DIN / BKB;     // 32
static constexpr int STAGES = 3;
static constexpr int A_BYTES = BM * BKB;     // 16384
static constexpr int B_BYTES = BN * BKB;     // 16384
static constexpr int TX_BYTES = A_BYTES + B_BYTES;

// SMEM layout
static constexpr int SM_FULL  = 0;
static constexpr int SM_EMPTY = SM_FULL + 8 * STAGES;
static constexpr int SM_A     = 1024;
static constexpr int SM_B     = SM_A + STAGES * A_BYTES;        // 50176
static constexpr int SMEM_TOTAL = SM_B + STAGES * B_BYTES;      // 99328 -> 2 CTAs/SM

static constexpr int AX_BLOCKS = 2048;   // amax blocks for x
static constexpr int AW_BLOCKS = 1024;   // amax blocks for W
static constexpr int QX_BLOCKS = 2048;
static constexpr int QW_BLOCKS = 1024;

// ---------------- scratch ----------------
__device__ uint8_t g_xq[(size_t)MROWS * DIN];
__device__ uint8_t g_wq[(size_t)DOUT * DIN];
__device__ float g_part_x[AX_BLOCKS];
__device__ float g_part_w[AW_BLOCKS];
__device__ float g_scale;   // sx*sw

// ---------------- PTX helpers ----------------
__device__ __forceinline__ uint32_t smem_u32(const void* p) {
    return (uint32_t)__cvta_generic_to_shared(p);
}

#define MBAR_INIT(addr, cnt) \
    asm volatile("mbarrier.init.shared.b64 [%0], %1;" :: "r"(addr), "r"((uint32_t)(cnt)) : "memory")

#define MBAR_EXPECT_TX(addr, bytes) \
    asm volatile("mbarrier.arrive.expect_tx.shared.b64 _, [%0], %1;" \
                 :: "r"(addr), "r"((uint32_t)(bytes)) : "memory")

#define MBAR_ARRIVE(addr) \
    asm volatile("mbarrier.arrive.shared.b64 _, [%0];" :: "r"(addr) : "memory")

#define MBAR_WAIT(addr, parity) do {                                            \
    asm volatile("{\n\t.reg .pred P1;\n\t"                                      \
        "WAIT_LOOP_%=:\n\t"                                                     \
        "mbarrier.try_wait.parity.acquire.cta.shared::cta.b64 P1, [%0], %1, 0x989680;\n\t" \
        "@P1 bra.uni WAIT_DONE_%=;\n\t"                                         \
        "bra.uni WAIT_LOOP_%=;\n\t"                                             \
        "WAIT_DONE_%=:\n\t}"                                                    \
        :: "r"(addr), "r"((uint32_t)(parity)) : "memory");                      \
} while (0)

#define MBAR_WAIT_RELAXED(addr, parity) do {                                    \
    asm volatile("{\n\t.reg .pred P1;\n\t"                                      \
        "WAIT_LOOP_%=:\n\t"                                                     \
        "mbarrier.try_wait.parity.relaxed.cta.shared::cta.b64 P1, [%0], %1, 0x989680;\n\t" \
        "@P1 bra.uni WAIT_DONE_%=;\n\t"                                         \
        "bra.uni WAIT_LOOP_%=;\n\t"                                             \
        "WAIT_DONE_%=:\n\t}"                                                    \
        :: "r"(addr), "r"((uint32_t)(parity)) : "memory");                      \
} while (0)

__device__ __forceinline__ void tma_load_2d(uint32_t dst_smem, const CUtensorMap* map,
                                            int cx, int cy, uint32_t mbar) {
    asm volatile(
        "cp.async.bulk.tensor.2d.shared::cta.global.tile.mbarrier::complete_tx::bytes "
        "[%0], [%1, {%2, %3}], [%4];"
        :: "r"(dst_smem), "l"(map), "r"(cx), "r"(cy), "r"(mbar) : "memory");
}

// LDSM: volatile (must stay ordered after the mbarrier acquire wait)
#define LDSM_X4(r0, r1, r2, r3, addr) \
    asm volatile("ldmatrix.sync.aligned.m8n8.x4.shared.b16 {%0,%1,%2,%3}, [%4];" \
                 : "=r"(r0), "=r"(r1), "=r"(r2), "=r"(r3) : "r"(addr))

// MMA: non-volatile — data deps fully constrain it
#define MMA_E4M3(d, a0, a1, a2, a3, b0, b1) \
    asm("mma.sync.aligned.m16n8k32.row.col.f32.e4m3.e4m3.f32 " \
        "{%0,%1,%2,%3}, {%4,%5,%6,%7}, {%8,%9}, {%0,%1,%2,%3};" \
        : "+f"((d)[0]), "+f"((d)[1]), "+f"((d)[2]), "+f"((d)[3]) \
        : "r"(a0), "r"(a1), "r"(a2), "r"(a3), "r"(b0), "r"(b1))

// packed e4m3x2 convert: first operand -> high byte, second -> low byte
#define CVT_E4M3X2(dst16, hi, lo) \
    asm("cvt.rn.satfinite.e4m3x2.f32 %0, %1, %2;" : "=h"(dst16) : "f"(hi), "f"(lo))

// ---------------- block reduce max (256 threads) ----------------
__device__ __forceinline__ float block_max_256(float m, float* sred) {
    #pragma unroll
    for (int o = 16; o > 0; o >>= 1)
        m = fmaxf(m, __shfl_xor_sync(0xFFFFFFFFu, m, o));
    if ((threadIdx.x & 31) == 0) sred[threadIdx.x >> 5] = m;
    __syncthreads();
    if (threadIdx.x < 8) {
        float v = sred[threadIdx.x];
        #pragma unroll
        for (int o = 4; o > 0; o >>= 1)
            v = fmaxf(v, __shfl_xor_sync(0xFFu, v, o));
        if (threadIdx.x == 0) sred[0] = v;
    }
    __syncthreads();
    return sred[0];
}

__device__ __forceinline__ float max4(float4 v) {
    return fmaxf(fmaxf(fabsf(v.x), fabsf(v.y)), fmaxf(fabsf(v.z), fabsf(v.w)));
}

// ---------------- prep kernels ----------------
// Fused amax for BOTH tensors in one launch: blocks [0, AX_BLOCKS) -> x,
// [AX_BLOCKS, ...) -> W. x2 unrolled: two independent float4 loads in flight
// per iteration (MLP sweet spot measured in R13/R14: 80.6% DRAM).
__global__ void amax_kernel(const float* __restrict__ x, const float* __restrict__ W) {
    __shared__ float sred[8];
    const bool isW = blockIdx.x >= AX_BLOCKS;
    const float4* s4 = isW ? (const float4*)W : (const float4*)x;
    const long long n4 = isW ? (long long)DOUT * DIN / 4 : (long long)MROWS * DIN / 4;
    const int nb = isW ? AW_BLOCKS : AX_BLOCKS;
    const int bid = isW ? (int)blockIdx.x - AX_BLOCKS : (int)blockIdx.x;

    // n4 is a multiple of 2*nb*256 for both splits, so the x2-unrolled loop
    // covers the range exactly.
    float m0 = 0.0f, m1 = 0.0f;
    const long long step = (long long)nb * blockDim.x;
    for (long long i = (long long)bid * blockDim.x + threadIdx.x; i < n4; i += 2 * step) {
        float4 a = s4[i];
        float4 b = s4[i + step];
        m0 = fmaxf(m0, max4(a));
        m1 = fmaxf(m1, max4(b));
    }
    float m = block_max_256(fmaxf(m0, m1), sred);
    if (threadIdx.x == 0) (isW ? g_part_w : g_part_x)[bid] = m;
}

// Fused quant for both tensors. Blocks [0,QX_BLOCKS) -> x, rest -> W.
// ALU-lean (reciprocal-mul + packed e4m3x2 CVT) and x2 unrolled for MLP.
__global__ void quant_kernel(const float* __restrict__ x, const float* __restrict__ W) {
    __shared__ float sred[8];
    const bool isW = blockIdx.x >= QX_BLOCKS;

    float m = 0.0f;
    if (isW) {
        for (int i = threadIdx.x; i < AW_BLOCKS; i += 256) m = fmaxf(m, g_part_w[i]);
    } else {
        for (int i = threadIdx.x; i < AX_BLOCKS; i += 256) m = fmaxf(m, g_part_x[i]);
    }
    m = block_max_256(m, sred);
    const float r = 448.0f / fmaxf(m, 1e-12f);   // exact once; per-element mul below

    if (blockIdx.x == 0) {
        __syncthreads();
        float mw = 0.0f;
        for (int i = threadIdx.x; i < AW_BLOCKS; i += 256) mw = fmaxf(mw, g_part_w[i]);
        mw = block_max_256(mw, sred);
        if (threadIdx.x == 0)
            g_scale = (fmaxf(m, 1e-12f) / 448.0f) * (fmaxf(mw, 1e-12f) / 448.0f);
    }

    const float4* s4 = isW ? (const float4*)W : (const float4*)x;
    uint8_t* dst = isW ? g_wq : g_xq;
    const long long n4 = isW ? (long long)DOUT * DIN / 4 : (long long)MROWS * DIN / 4;
    const int nb = isW ? QW_BLOCKS : QX_BLOCKS;
    const int bid = isW ? (int)blockIdx.x - QX_BLOCKS : (int)blockIdx.x;

    // exact coverage: n4 is a multiple of 2*nb*256
    const long long step = (long long)nb * blockDim.x;
    for (long long i = (long long)bid * blockDim.x + threadIdx.x; i < n4; i += 2 * step) {
        float4 a = s4[i];
        float4 b = s4[i + step];
        unsigned short lo0, hi0, lo1, hi1;
        CVT_E4M3X2(lo0, a.y * r, a.x * r);
        CVT_E4M3X2(hi0, a.w * r, a.z * r);
        CVT_E4M3X2(lo1, b.y * r, b.x * r);
        CVT_E4M3X2(hi1, b.w * r, b.z * r);
        *reinterpret_cast<uint32_t*>(dst + i * 4)          = (uint32_t)lo0 | ((uint32_t)hi0 << 16);
        *reinterpret_cast<uint32_t*>(dst + (i + step) * 4) = (uint32_t)lo1 | ((uint32_t)hi1 << 16);
    }
}

// ---------------- GEMM: TMA pipeline + fp8 mma.sync (frozen round-9/11 winner) ----------------
#define LOAD_FRAGS(ks, A, B) do {                                               \
    _Pragma("unroll")                                                           \
    for (int mt = 0; mt < 2; ++mt)                                              \
        LDSM_X4((A)[mt][0], (A)[mt][1], (A)[mt][2], (A)[mt][3],                 \
                aBase + mt * (16 * BKB) + cAo[ks]);                             \
    _Pragma("unroll")                                                           \
    for (int g = 0; g < 4; ++g)                                                 \
        LDSM_X4((B)[2*g][0], (B)[2*g][1], (B)[2*g+1][0], (B)[2*g+1][1],         \
                bBase + g * (16 * BKB) + cBo[ks]);                              \
} while (0)

#define MMA_BURST(A, B) do {                                                    \
    _Pragma("unroll")                                                           \
    for (int mt = 0; mt < 2; ++mt)                                              \
        _Pragma("unroll")                                                       \
        for (int nt = 0; nt < 8; ++nt)                                          \
            MMA_E4M3(acc[mt][nt],                                               \
                     (A)[mt][0], (A)[mt][1], (A)[mt][2], (A)[mt][3],            \
                     (B)[nt][0], (B)[nt][1]);                                   \
} while (0)

__global__ void __launch_bounds__(256, 2) gemm_kernel(
    const __grid_constant__ CUtensorMap tma_a,
    const __grid_constant__ CUtensorMap tma_b,
    const float* __restrict__ bias,
    float* __restrict__ out)
{
    extern __shared__ __align__(1024) char smem[];
    const uint32_t sbase = smem_u32(smem);
    const int tid  = threadIdx.x;
    const int wid  = tid >> 5;
    const int lane = tid & 31;
    const int warpM = wid & 3;    // 0..3 (32 rows each)
    const int warpN = wid >> 2;   // 0..1 (64 cols each)

    if (tid == 0) {
        #pragma unroll
        for (int s = 0; s < STAGES; s++) {
            MBAR_INIT(sbase + SM_FULL + 8 * s, 1);
            MBAR_INIT(sbase + SM_EMPTY + 8 * s, 8);
        }
        asm volatile("fence.proxy.async.shared::cta;" ::: "memory");
    }
    __syncthreads();

    const int mbase = (int)blockIdx.y * BM;
    const int nbase = (int)blockIdx.x * BN;

    // prologue: fill STAGES-1 stages
    if (tid == 0) {
        #pragma unroll
        for (int f = 0; f < STAGES - 1; ++f) {
            MBAR_EXPECT_TX(sbase + SM_FULL + 8 * f, TX_BYTES);
            tma_load_2d(sbase + SM_A + f * A_BYTES, &tma_a, f * BKB, mbase, sbase + SM_FULL + 8 * f);
            tma_load_2d(sbase + SM_B + f * B_BYTES, &tma_b, f * BKB, nbase, sbase + SM_FULL + 8 * f);
        }
    }

    // per-lane ldmatrix address precompute (SW128 swizzle: 16B-chunk ^ (row & 7))
    const int l8 = lane & 7;
    const int rowA  = warpM * 32 + l8 + 8 * ((lane >> 3) & 1);
    const int halfA = lane >> 4;
    const int swzA  = rowA & 7;
    const uint32_t aRowOff = (uint32_t)rowA * BKB;
    const int rowB  = warpN * 64 + l8 + 8 * (lane >> 4);
    const int halfB = (lane >> 3) & 1;
    const int swzB  = rowB & 7;
    const uint32_t bRowOff = (uint32_t)rowB * BKB;

    // precomputed swizzled chunk offsets for the 4 k32 slices (loop-invariant)
    uint32_t cAo[4], cBo[4];
    #pragma unroll
    for (int ks = 0; ks < 4; ++ks) {
        cAo[ks] = (uint32_t)((((ks << 1) | halfA) ^ swzA) << 4);
        cBo[ks] = (uint32_t)((((ks << 1) | halfB) ^ swzB) << 4);
    }

    float acc[2][8][4];
    #pragma unroll
    for (int mt = 0; mt < 2; ++mt)
        #pragma unroll
        for (int nt = 0; nt < 8; ++nt)
            #pragma unroll
            for (int r = 0; r < 4; ++r) acc[mt][nt][r] = 0.0f;

    uint32_t afr[2][2][4];
    uint32_t bfr[2][8][2];

    // unroll by STAGES so stage indices fold to immediates without a 50KB body
    #pragma unroll 3
    for (int i = 0; i < KITERS; ++i) {
        const int s = i % STAGES;
        const uint32_t ph = (uint32_t)((i / STAGES) & 1);

        // rotate TMA producer duty across warps: iteration f's producer is warp (f & 7)
        {
            const int f = i + STAGES - 1;
            if (f < KITERS && wid == (f & 7) && lane == 0) {
                const int fs = f % STAGES;
                if (f >= STAGES) {
                    MBAR_WAIT_RELAXED(sbase + SM_EMPTY + 8 * fs,
                                      (uint32_t)(((f - STAGES) / STAGES) & 1));
                }
                MBAR_EXPECT_TX(sbase + SM_FULL + 8 * fs, TX_BYTES);
                tma_load_2d(sbase + SM_A + fs * A_BYTES, &tma_a, f * BKB, mbase, sbase + SM_FULL + 8 * fs);
                tma_load_2d(sbase + SM_B + fs * B_BYTES, &tma_b, f * BKB, nbase, sbase + SM_FULL + 8 * fs);
            }
        }

        MBAR_WAIT(sbase + SM_FULL + 8 * s, ph);

        const uint32_t aBase = sbase + SM_A + s * A_BYTES + aRowOff;
        const uint32_t bBase = sbase + SM_B + s * B_BYTES + bRowOff;

        // round-7 slice schedule: empty-arrive fires after the LAST LDSM
        LOAD_FRAGS(0, afr[0], bfr[0]);
        LOAD_FRAGS(1, afr[1], bfr[1]);
        MMA_BURST(afr[0], bfr[0]);
        LOAD_FRAGS(2, afr[0], bfr[0]);
        MMA_BURST(afr[1], bfr[1]);
        LOAD_FRAGS(3, afr[1], bfr[1]);
        if (lane == 0) MBAR_ARRIVE(sbase + SM_EMPTY + 8 * s);   // early release
        MMA_BURST(afr[0], bfr[0]);
        MMA_BURST(afr[1], bfr[1]);
    }

    // ---- epilogue ----
    const float sc = g_scale;
    const int orow0 = mbase + warpM * 32 + (lane >> 2);
    const int ocol0 = nbase + warpN * 64 + (lane & 3) * 2;

    #pragma unroll
    for (int mt = 0; mt < 2; ++mt) {
        #pragma unroll
        for (int nt = 0; nt < 8; ++nt) {
            const int col = ocol0 + nt * 8;
            const float2 bb = *reinterpret_cast<const float2*>(bias + col);
            const int r0 = orow0 + mt * 16;
            float2 v0, v1;
            v0.x = acc[mt][nt][0] * sc + bb.x;
            v0.y = acc[mt][nt][1] * sc + bb.y;
            v1.x = acc[mt][nt][2] * sc + bb.x;
            v1.y = acc[mt][nt][3] * sc + bb.y;
            *reinterpret_cast<float2*>(out + (size_t)r0 * DOUT + col) = v0;
            *reinterpret_cast<float2*>(out + (size_t)(r0 + 8) * DOUT + col) = v1;
        }
    }
}

// ---------------- host launch ----------------
typedef CUresult (*EncodeFn)(CUtensorMap*, CUtensorMapDataType, cuuint32_t, void*,
                             const cuuint64_t*, const cuuint64_t*, const cuuint32_t*,
                             const cuuint32_t*, CUtensorMapInterleave, CUtensorMapSwizzle,
                             CUtensorMapL2promotion, CUtensorMapFloatOOBfill);

static void make_map(EncodeFn enc, CUtensorMap* map, void* base,
                     uint64_t dim0, uint64_t dim1, uint32_t box0, uint32_t box1) {
    cuuint64_t dims[2]    = {dim0, dim1};
    cuuint64_t strides[1] = {dim0};   // 1 byte per element
    cuuint32_t box[2]     = {box0, box1};
    cuuint32_t estr[2]    = {1, 1};
    enc(map, CU_TENSOR_MAP_DATA_TYPE_UINT8, 2, base, dims, strides, box, estr,
        CU_TENSOR_MAP_INTERLEAVE_NONE, CU_TENSOR_MAP_SWIZZLE_128B,
        CU_TENSOR_MAP_L2_PROMOTION_L2_128B, CU_TENSOR_MAP_FLOAT_OOB_FILL_NONE);
}

extern "C" void kernel_launch(void* const* d_in, const int* in_sizes, int n_in,
                              void* d_out, int out_size) {
    const float* x    = (const float*)d_in[0];
    const float* W    = (const float*)d_in[1];
    const float* bias = (const float*)d_in[2];
    float* out        = (float*)d_out;

    void *xq_ptr = nullptr, *wq_ptr = nullptr;
    cudaGetSymbolAddress(&xq_ptr, g_xq);
    cudaGetSymbolAddress(&wq_ptr, g_wq);

    EncodeFn enc = nullptr;
    cudaDriverEntryPointQueryResult qres;
    cudaGetDriverEntryPointByVersion("cuTensorMapEncodeTiled", (void**)&enc, 12000,
                                     cudaEnableDefault, &qres);

    CUtensorMap tma_a, tma_b;
    make_map(enc, &tma_a, xq_ptr, DIN, MROWS, BKB, BM);
    make_map(enc, &tma_b, wq_ptr, DIN, DOUT, BKB, BN);

    cudaFuncSetAttribute(gemm_kernel, cudaFuncAttributeMaxDynamicSharedMemorySize, SMEM_TOTAL);

    // 3 launches: fused amax, fused quant, gemm.
    amax_kernel<<<AX_BLOCKS + AW_BLOCKS, 256>>>(x, W);
    quant_kernel<<<QX_BLOCKS + QW_BLOCKS, 256>>>(x, W);

    dim3 grid(DOUT / BN, MROWS / BM);   // (32, 64)
    gemm_kernel<<<grid, 256, SMEM_TOTAL>>>(tma_a, tma_b, bias, out);
}

// round 17
// speedup vs baseline: 1.0032x; 1.0010x over previous
#include <cuda_runtime.h>
#include <cuda.h>
#include <cuda_bf16.h>
#include <cuda_fp8.h>
#include <cstdint>

// Problem shape: x[4,2048,4096] -> M=8192, W[4096,4096], b[4096]
#define MROWS 8192
#define DIN   4096
#define DOUT  4096

// GEMM tiling: CTA 128x128, 8 warps (4 M x 2 N), warp tile 32x64, 2 CTAs/SM
static constexpr int BM = 128;
static constexpr int BN = 128;
static constexpr int BKB = 128;              // K bytes per stage (one SW128 row)
static constexpr int KITERS = DIN / BKB;     // 32
static constexpr int STAGES = 3;
static constexpr int A_BYTES = BM * BKB;     // 16384
static constexpr int B_BYTES = BN * BKB;     // 16384
static constexpr int TX_BYTES = A_BYTES + B_BYTES;

// SMEM layout
static constexpr int SM_FULL  = 0;
static constexpr int SM_EMPTY = SM_FULL + 8 * STAGES;
static constexpr int SM_A     = 1024;
static constexpr int SM_B     = SM_A + STAGES * A_BYTES;        // 50176
static constexpr int SMEM_TOTAL = SM_B + STAGES * B_BYTES;      // 99328 -> 2 CTAs/SM

static constexpr int AX_BLOCKS = 2048;   // amax blocks for x
static constexpr int AW_BLOCKS = 1024;   // amax blocks for W
static constexpr int QX_BLOCKS = 2048;
static constexpr int QW_BLOCKS = 1024;

// ---------------- scratch ----------------
__device__ uint8_t g_xq[(size_t)MROWS * DIN];
__device__ uint8_t g_wq[(size_t)DOUT * DIN];
__device__ float g_part_x[AX_BLOCKS];
__device__ float g_part_w[AW_BLOCKS];
__device__ float g_scale;   // sx*sw

// ---------------- PTX helpers ----------------
__device__ __forceinline__ uint32_t smem_u32(const void* p) {
    return (uint32_t)__cvta_generic_to_shared(p);
}

#define MBAR_INIT(addr, cnt) \
    asm volatile("mbarrier.init.shared.b64 [%0], %1;" :: "r"(addr), "r"((uint32_t)(cnt)) : "memory")

#define MBAR_EXPECT_TX(addr, bytes) \
    asm volatile("mbarrier.arrive.expect_tx.shared.b64 _, [%0], %1;" \
                 :: "r"(addr), "r"((uint32_t)(bytes)) : "memory")

#define MBAR_ARRIVE(addr) \
    asm volatile("mbarrier.arrive.shared.b64 _, [%0];" :: "r"(addr) : "memory")

#define MBAR_WAIT(addr, parity) do {                                            \
    asm volatile("{\n\t.reg .pred P1;\n\t"                                      \
        "WAIT_LOOP_%=:\n\t"                                                     \
        "mbarrier.try_wait.parity.acquire.cta.shared::cta.b64 P1, [%0], %1, 0x989680;\n\t" \
        "@P1 bra.uni WAIT_DONE_%=;\n\t"                                         \
        "bra.uni WAIT_LOOP_%=;\n\t"                                             \
        "WAIT_DONE_%=:\n\t}"                                                    \
        :: "r"(addr), "r"((uint32_t)(parity)) : "memory");                      \
} while (0)

#define MBAR_WAIT_RELAXED(addr, parity) do {                                    \
    asm volatile("{\n\t.reg .pred P1;\n\t"                                      \
        "WAIT_LOOP_%=:\n\t"                                                     \
        "mbarrier.try_wait.parity.relaxed.cta.shared::cta.b64 P1, [%0], %1, 0x989680;\n\t" \
        "@P1 bra.uni WAIT_DONE_%=;\n\t"                                         \
        "bra.uni WAIT_LOOP_%=;\n\t"                                             \
        "WAIT_DONE_%=:\n\t}"                                                    \
        :: "r"(addr), "r"((uint32_t)(parity)) : "memory");                      \
} while (0)

__device__ __forceinline__ void tma_load_2d(uint32_t dst_smem, const CUtensorMap* map,
                                            int cx, int cy, uint32_t mbar) {
    asm volatile(
        "cp.async.bulk.tensor.2d.shared::cta.global.tile.mbarrier::complete_tx::bytes "
        "[%0], [%1, {%2, %3}], [%4];"
        :: "r"(dst_smem), "l"(map), "r"(cx), "r"(cy), "r"(mbar) : "memory");
}

// LDSM: volatile (must stay ordered after the mbarrier acquire wait)
#define LDSM_X4(r0, r1, r2, r3, addr) \
    asm volatile("ldmatrix.sync.aligned.m8n8.x4.shared.b16 {%0,%1,%2,%3}, [%4];" \
                 : "=r"(r0), "=r"(r1), "=r"(r2), "=r"(r3) : "r"(addr))

// MMA: non-volatile — data deps fully constrain it
#define MMA_E4M3(d, a0, a1, a2, a3, b0, b1) \
    asm("mma.sync.aligned.m16n8k32.row.col.f32.e4m3.e4m3.f32 " \
        "{%0,%1,%2,%3}, {%4,%5,%6,%7}, {%8,%9}, {%0,%1,%2,%3};" \
        : "+f"((d)[0]), "+f"((d)[1]), "+f"((d)[2]), "+f"((d)[3]) \
        : "r"(a0), "r"(a1), "r"(a2), "r"(a3), "r"(b0), "r"(b1))

// packed e4m3x2 convert: first operand -> high byte, second -> low byte
#define CVT_E4M3X2(dst16, hi, lo) \
    asm("cvt.rn.satfinite.e4m3x2.f32 %0, %1, %2;" : "=h"(dst16) : "f"(hi), "f"(lo))

// ---------------- block reduce max (256 threads) ----------------
__device__ __forceinline__ float block_max_256(float m, float* sred) {
    #pragma unroll
    for (int o = 16; o > 0; o >>= 1)
        m = fmaxf(m, __shfl_xor_sync(0xFFFFFFFFu, m, o));
    if ((threadIdx.x & 31) == 0) sred[threadIdx.x >> 5] = m;
    __syncthreads();
    if (threadIdx.x < 8) {
        float v = sred[threadIdx.x];
        #pragma unroll
        for (int o = 4; o > 0; o >>= 1)
            v = fmaxf(v, __shfl_xor_sync(0xFFu, v, o));
        if (threadIdx.x == 0) sred[0] = v;
    }
    __syncthreads();
    return sred[0];
}

__device__ __forceinline__ float max4(float4 v) {
    return fmaxf(fmaxf(fabsf(v.x), fabsf(v.y)), fmaxf(fabsf(v.z), fabsf(v.w)));
}

// ---------------- prep kernels ----------------
// Fused amax for BOTH tensors in one launch: blocks [0, AX_BLOCKS) -> x,
// [AX_BLOCKS, ...) -> W. x2 unrolled: two independent float4 loads in flight
// per iteration (measured MLP sweet spot: ~79-81% DRAM).
__global__ void amax_kernel(const float* __restrict__ x, const float* __restrict__ W) {
    __shared__ float sred[8];
    const bool isW = blockIdx.x >= AX_BLOCKS;
    const float4* s4 = isW ? (const float4*)W : (const float4*)x;
    const long long n4 = isW ? (long long)DOUT * DIN / 4 : (long long)MROWS * DIN / 4;
    const int nb = isW ? AW_BLOCKS : AX_BLOCKS;
    const int bid = isW ? (int)blockIdx.x - AX_BLOCKS : (int)blockIdx.x;

    // n4 is a multiple of 2*nb*256 for both splits -> exact coverage.
    float m0 = 0.0f, m1 = 0.0f;
    const long long step = (long long)nb * blockDim.x;
    for (long long i = (long long)bid * blockDim.x + threadIdx.x; i < n4; i += 2 * step) {
        float4 a = s4[i];
        float4 b = s4[i + step];
        m0 = fmaxf(m0, max4(a));
        m1 = fmaxf(m1, max4(b));
    }
    float m = block_max_256(fmaxf(m0, m1), sred);
    if (threadIdx.x == 0) (isW ? g_part_w : g_part_x)[bid] = m;
}

// Fused quant for both tensors. Blocks [0,QX_BLOCKS) -> x, rest -> W.
// ALU-lean (reciprocal-mul + packed e4m3x2 CVT), x2 unrolled for MLP.
__global__ void quant_kernel(const float* __restrict__ x, const float* __restrict__ W) {
    __shared__ float sred[8];
    const bool isW = blockIdx.x >= QX_BLOCKS;

    float m = 0.0f;
    if (isW) {
        for (int i = threadIdx.x; i < AW_BLOCKS; i += 256) m = fmaxf(m, g_part_w[i]);
    } else {
        for (int i = threadIdx.x; i < AX_BLOCKS; i += 256) m = fmaxf(m, g_part_x[i]);
    }
    m = block_max_256(m, sred);
    const float r = 448.0f / fmaxf(m, 1e-12f);   // exact once; per-element mul below

    if (blockIdx.x == 0) {
        __syncthreads();
        float mw = 0.0f;
        for (int i = threadIdx.x; i < AW_BLOCKS; i += 256) mw = fmaxf(mw, g_part_w[i]);
        mw = block_max_256(mw, sred);
        if (threadIdx.x == 0)
            g_scale = (fmaxf(m, 1e-12f) / 448.0f) * (fmaxf(mw, 1e-12f) / 448.0f);
    }

    const float4* s4 = isW ? (const float4*)W : (const float4*)x;
    uint8_t* dst = isW ? g_wq : g_xq;
    const long long n4 = isW ? (long long)DOUT * DIN / 4 : (long long)MROWS * DIN / 4;
    const int nb = isW ? QW_BLOCKS : QX_BLOCKS;
    const int bid = isW ? (int)blockIdx.x - QX_BLOCKS : (int)blockIdx.x;

    // exact coverage: n4 is a multiple of 2*nb*256
    const long long step = (long long)nb * blockDim.x;
    for (long long i = (long long)bid * blockDim.x + threadIdx.x; i < n4; i += 2 * step) {
        float4 a = s4[i];
        float4 b = s4[i + step];
        unsigned short lo0, hi0, lo1, hi1;
        CVT_E4M3X2(lo0, a.y * r, a.x * r);
        CVT_E4M3X2(hi0, a.w * r, a.z * r);
        CVT_E4M3X2(lo1, b.y * r, b.x * r);
        CVT_E4M3X2(hi1, b.w * r, b.z * r);
        *reinterpret_cast<uint32_t*>(dst + i * 4)          = (uint32_t)lo0 | ((uint32_t)hi0 << 16);
        *reinterpret_cast<uint32_t*>(dst + (i + step) * 4) = (uint32_t)lo1 | ((uint32_t)hi1 << 16);
    }
}

// ---------------- GEMM: TMA pipeline + fp8 mma.sync (frozen round-9/11 winner) ----------------
#define LOAD_FRAGS(ks, A, B) do {                                               \
    _Pragma("unroll")                                                           \
    for (int mt = 0; mt < 2; ++mt)                                              \
        LDSM_X4((A)[mt][0], (A)[mt][1], (A)[mt][2], (A)[mt][3],                 \
                aBase + mt * (16 * BKB) + cAo[ks]);                             \
    _Pragma("unroll")                                                           \
    for (int g = 0; g < 4; ++g)                                                 \
        LDSM_X4((B)[2*g][0], (B)[2*g][1], (B)[2*g+1][0], (B)[2*g+1][1],         \
                bBase + g * (16 * BKB) + cBo[ks]);                              \
} while (0)

#define MMA_BURST(A, B) do {                                                    \
    _Pragma("unroll")                                                           \
    for (int mt = 0; mt < 2; ++mt)                                              \
        _Pragma("unroll")                                                       \
        for (int nt = 0; nt < 8; ++nt)                                          \
            MMA_E4M3(acc[mt][nt],                                               \
                     (A)[mt][0], (A)[mt][1], (A)[mt][2], (A)[mt][3],            \
                     (B)[nt][0], (B)[nt][1]);                                   \
} while (0)

__global__ void __launch_bounds__(256, 2) gemm_kernel(
    const __grid_constant__ CUtensorMap tma_a,
    const __grid_constant__ CUtensorMap tma_b,
    const float* __restrict__ bias,
    float* __restrict__ out)
{
    extern __shared__ __align__(1024) char smem[];
    const uint32_t sbase = smem_u32(smem);
    const int tid  = threadIdx.x;
    const int wid  = tid >> 5;
    const int lane = tid & 31;
    const int warpM = wid & 3;    // 0..3 (32 rows each)
    const int warpN = wid >> 2;   // 0..1 (64 cols each)

    if (tid == 0) {
        #pragma unroll
        for (int s = 0; s < STAGES; s++) {
            MBAR_INIT(sbase + SM_FULL + 8 * s, 1);
            MBAR_INIT(sbase + SM_EMPTY + 8 * s, 8);
        }
        asm volatile("fence.proxy.async.shared::cta;" ::: "memory");
    }
    __syncthreads();

    const int mbase = (int)blockIdx.y * BM;
    const int nbase = (int)blockIdx.x * BN;

    // prologue: fill STAGES-1 stages
    if (tid == 0) {
        #pragma unroll
        for (int f = 0; f < STAGES - 1; ++f) {
            MBAR_EXPECT_TX(sbase + SM_FULL + 8 * f, TX_BYTES);
            tma_load_2d(sbase + SM_A + f * A_BYTES, &tma_a, f * BKB, mbase, sbase + SM_FULL + 8 * f);
            tma_load_2d(sbase + SM_B + f * B_BYTES, &tma_b, f * BKB, nbase, sbase + SM_FULL + 8 * f);
        }
    }

    // per-lane ldmatrix address precompute (SW128 swizzle: 16B-chunk ^ (row & 7))
    const int l8 = lane & 7;
    const int rowA  = warpM * 32 + l8 + 8 * ((lane >> 3) & 1);
    const int halfA = lane >> 4;
    const int swzA  = rowA & 7;
    const uint32_t aRowOff = (uint32_t)rowA * BKB;
    const int rowB  = warpN * 64 + l8 + 8 * (lane >> 4);
    const int halfB = (lane >> 3) & 1;
    const int swzB  = rowB & 7;
    const uint32_t bRowOff = (uint32_t)rowB * BKB;

    // precomputed swizzled chunk offsets for the 4 k32 slices (loop-invariant)
    uint32_t cAo[4], cBo[4];
    #pragma unroll
    for (int ks = 0; ks < 4; ++ks) {
        cAo[ks] = (uint32_t)((((ks << 1) | halfA) ^ swzA) << 4);
        cBo[ks] = (uint32_t)((((ks << 1) | halfB) ^ swzB) << 4);
    }

    float acc[2][8][4];
    #pragma unroll
    for (int mt = 0; mt < 2; ++mt)
        #pragma unroll
        for (int nt = 0; nt < 8; ++nt)
            #pragma unroll
            for (int r = 0; r < 4; ++r) acc[mt][nt][r] = 0.0f;

    uint32_t afr[2][2][4];
    uint32_t bfr[2][8][2];

    // unroll by STAGES so stage indices fold to immediates without a 50KB body
    #pragma unroll 3
    for (int i = 0; i < KITERS; ++i) {
        const int s = i % STAGES;
        const uint32_t ph = (uint32_t)((i / STAGES) & 1);

        // rotate TMA producer duty across warps: iteration f's producer is warp (f & 7)
        {
            const int f = i + STAGES - 1;
            if (f < KITERS && wid == (f & 7) && lane == 0) {
                const int fs = f % STAGES;
                if (f >= STAGES) {
                    MBAR_WAIT_RELAXED(sbase + SM_EMPTY + 8 * fs,
                                      (uint32_t)(((f - STAGES) / STAGES) & 1));
                }
                MBAR_EXPECT_TX(sbase + SM_FULL + 8 * fs, TX_BYTES);
                tma_load_2d(sbase + SM_A + fs * A_BYTES, &tma_a, f * BKB, mbase, sbase + SM_FULL + 8 * fs);
                tma_load_2d(sbase + SM_B + fs * B_BYTES, &tma_b, f * BKB, nbase, sbase + SM_FULL + 8 * fs);
            }
        }

        MBAR_WAIT(sbase + SM_FULL + 8 * s, ph);

        const uint32_t aBase = sbase + SM_A + s * A_BYTES + aRowOff;
        const uint32_t bBase = sbase + SM_B + s * B_BYTES + bRowOff;

        // round-7 slice schedule: empty-arrive fires after the LAST LDSM
        LOAD_FRAGS(0, afr[0], bfr[0]);
        LOAD_FRAGS(1, afr[1], bfr[1]);
        MMA_BURST(afr[0], bfr[0]);
        LOAD_FRAGS(2, afr[0], bfr[0]);
        MMA_BURST(afr[1], bfr[1]);
        LOAD_FRAGS(3, afr[1], bfr[1]);
        if (lane == 0) MBAR_ARRIVE(sbase + SM_EMPTY + 8 * s);   // early release
        MMA_BURST(afr[0], bfr[0]);
        MMA_BURST(afr[1], bfr[1]);
    }

    // ---- epilogue ----
    const float sc = g_scale;
    const int orow0 = mbase + warpM * 32 + (lane >> 2);
    const int ocol0 = nbase + warpN * 64 + (lane & 3) * 2;

    #pragma unroll
    for (int mt = 0; mt < 2; ++mt) {
        #pragma unroll
        for (int nt = 0; nt < 8; ++nt) {
            const int col = ocol0 + nt * 8;
            const float2 bb = *reinterpret_cast<const float2*>(bias + col);
            const int r0 = orow0 + mt * 16;
            float2 v0, v1;
            v0.x = acc[mt][nt][0] * sc + bb.x;
            v0.y = acc[mt][nt][1] * sc + bb.y;
            v1.x = acc[mt][nt][2] * sc + bb.x;
            v1.y = acc[mt][nt][3] * sc + bb.y;
            *reinterpret_cast<float2*>(out + (size_t)r0 * DOUT + col) = v0;
            *reinterpret_cast<float2*>(out + (size_t)(r0 + 8) * DOUT + col) = v1;
        }
    }
}

// ---------------- host launch ----------------
typedef CUresult (*EncodeFn)(CUtensorMap*, CUtensorMapDataType, cuuint32_t, void*,
                             const cuuint64_t*, const cuuint64_t*, const cuuint32_t*,
                             const cuuint32_t*, CUtensorMapInterleave, CUtensorMapSwizzle,
                             CUtensorMapL2promotion, CUtensorMapFloatOOBfill);

static void make_map(EncodeFn enc, CUtensorMap* map, void* base,
                     uint64_t dim0, uint64_t dim1, uint32_t box0, uint32_t box1) {
    cuuint64_t dims[2]    = {dim0, dim1};
    cuuint64_t strides[1] = {dim0};   // 1 byte per element
    cuuint32_t box[2]     = {box0, box1};
    cuuint32_t estr[2]    = {1, 1};
    enc(map, CU_TENSOR_MAP_DATA_TYPE_UINT8, 2, base, dims, strides, box, estr,
        CU_TENSOR_MAP_INTERLEAVE_NONE, CU_TENSOR_MAP_SWIZZLE_128B,
        CU_TENSOR_MAP_L2_PROMOTION_L2_128B, CU_TENSOR_MAP_FLOAT_OOB_FILL_NONE);
}

extern "C" void kernel_launch(void* const* d_in, const int* in_sizes, int n_in,
                              void* d_out, int out_size) {
    const float* x    = (const float*)d_in[0];
    const float* W    = (const float*)d_in[1];
    const float* bias = (const float*)d_in[2];
    float* out        = (float*)d_out;

    void *xq_ptr = nullptr, *wq_ptr = nullptr;
    cudaGetSymbolAddress(&xq_ptr, g_xq);
    cudaGetSymbolAddress(&wq_ptr, g_wq);

    EncodeFn enc = nullptr;
    cudaDriverEntryPointQueryResult qres;
    cudaGetDriverEntryPointByVersion("cuTensorMapEncodeTiled", (void**)&enc, 12000,
                                     cudaEnableDefault, &qres);

    CUtensorMap tma_a, tma_b;
    make_map(enc, &tma_a, xq_ptr, DIN, MROWS, BKB, BM);
    make_map(enc, &tma_b, wq_ptr, DIN, DOUT, BKB, BN);

    cudaFuncSetAttribute(gemm_kernel, cudaFuncAttributeMaxDynamicSharedMemorySize, SMEM_TOTAL);

    // 3 launches: fused amax, fused quant, gemm.
    amax_kernel<<<AX_BLOCKS + AW_BLOCKS, 256>>>(x, W);
    quant_kernel<<<QX_BLOCKS + QW_BLOCKS, 256>>>(x, W);

    dim3 grid(DOUT / BN, MROWS / BM);   // (32, 64)
    gemm_kernel<<<grid, 256, SMEM_TOTAL>>>(tma_a, tma_b, bias, out);
}